// round 4
// baseline (speedup 1.0000x reference)
#include <cuda_runtime.h>
#include <cuda_bf16.h>
#include <cstdint>

#define NN   50000
#define NPAD 50048          // 391 * 128
#define NE   400000
#define HID  128
#define NLAY 3
#define NG   512

#define WPAD 136            // padded row length (halves) for ldmatrix conflict-freedom
#define WIMG_B (128*WPAD*2) // 34816 bytes per bf16 image
#define WMAT_B (2*WIMG_B)   // hi + lo per matrix

// ---------------- scratch ----------------
__device__ float g_h  [NPAD*HID];
__device__ float g_hn [NPAD*HID];
__device__ float g_q  [NPAD*HID];
__device__ float g_k  [NPAD*HID];
__device__ float g_v  [NPAD*HID];
__device__ float g_xr [NPAD*HID];
__device__ float g_f1 [NPAD*HID];
__device__ float g_f2 [NPAD*HID];
__device__ float g_efeat[NE*10];
__device__ float g_w   [NE*4];      // raw logits, then exp weights
__device__ unsigned g_maxi[NN*4];
__device__ float    g_ssum[NN*4];
__device__ int   g_deg[NN];
__device__ int   g_rowptr[NN+1];
__device__ int   g_cursor[NN];
__device__ int   g_csr[NE];
__device__ float g_pooled[NG*HID];
__device__ char  g_wimg[21*WMAT_B]; // 21 matrices x {hi,lo} padded bf16 images of W^T

__device__ __forceinline__ float sp_f(float x){ return x > 20.f ? x : log1pf(expf(x)); }

__device__ __forceinline__ unsigned fkey(float f){
    unsigned b = __float_as_uint(f);
    return (b & 0x80000000u) ? ~b : (b | 0x80000000u);
}
__device__ __forceinline__ float funkey(unsigned k){
    unsigned b = (k & 0x80000000u) ? (k & 0x7fffffffu) : ~k;
    return __uint_as_float(b);
}

__device__ __forceinline__ uint32_t smem_u32(const void* p){
    uint32_t a;
    asm("{ .reg .u64 t; cvta.to.shared.u64 t, %1; cvt.u32.u64 %0, t; }" : "=r"(a) : "l"(p));
    return a;
}
__device__ __forceinline__ void ldsm4(uint32_t addr, uint32_t* r){
    asm volatile("ldmatrix.sync.aligned.m8n8.x4.shared.b16 {%0,%1,%2,%3}, [%4];"
        : "=r"(r[0]), "=r"(r[1]), "=r"(r[2]), "=r"(r[3]) : "r"(addr));
}
__device__ __forceinline__ void mma16816(float* c, const uint32_t* a, uint32_t b0, uint32_t b1){
    asm volatile(
        "mma.sync.aligned.m16n8k16.row.col.f32.bf16.bf16.f32 "
        "{%0,%1,%2,%3}, {%4,%5,%6,%7}, {%8,%9}, {%0,%1,%2,%3};"
        : "+f"(c[0]), "+f"(c[1]), "+f"(c[2]), "+f"(c[3])
        : "r"(a[0]), "r"(a[1]), "r"(a[2]), "r"(a[3]), "r"(b0), "r"(b1));
}

// SMEM layout for GEMM (dynamic): A_hi | A_lo | W_hi | W_lo, each 128 x 136 bf16
#define SM_A_HI 0
#define SM_A_LO WIMG_B
#define SM_W_HI (2*WIMG_B)
#define SM_W_LO (3*WIMG_B)
#define SM_BYTES (4*WIMG_B)   // 139264

// ---------------- init / zero ----------------
__global__ void k_init(const float* __restrict__ h){
    int i = blockIdx.x*256 + threadIdx.x;
    if(i < NPAD*HID) g_h[i] = (i < NN*HID) ? h[i] : 0.f;
}
__global__ void k_zero_all(){
    int i = blockIdx.x*256 + threadIdx.x;
    if(i < NN){ g_deg[i] = 0; g_cursor[i] = 0; }
    if(i < NG*HID) g_pooled[i] = 0.f;
}
__global__ void k_zero_attn(){
    int i = blockIdx.x*256 + threadIdx.x;
    if(i < NN*4){ g_maxi[i] = 0u; g_ssum[i] = 0.f; }
}

// ---------------- weight prep: W^T + bf16 hi/lo padded images ----------------
__global__ void k_prepw(const float* Wq, const float* Wk, const float* Wv, const float* Ws,
                        const float* W1, const float* W2, const float* W3){
    int idx = blockIdx.x*256 + threadIdx.x;
    if(idx >= 21*16384) return;
    int m = idx >> 14;          // 0..20 = fam*3 + layer
    int within = idx & 16383;
    int n = within >> 7, k2 = within & 127;
    int fam = m/3, layer = m - fam*3;
    const float* W;
    switch(fam){
        case 0: W = Wq; break; case 1: W = Wk; break; case 2: W = Wv; break;
        case 3: W = Ws; break; case 4: W = W1; break; case 5: W = W2; break;
        default: W = W3; break;
    }
    float w = W[layer*16384 + k2*128 + n];       // Wt[n][k] = W[k][n]
    __nv_bfloat16 hi = __float2bfloat16(w);
    __nv_bfloat16 lo = __float2bfloat16(w - __bfloat162float(hi));
    char* base = g_wimg + (size_t)m*WMAT_B;
    int off = (n*WPAD + k2)*2;
    *(__nv_bfloat16*)(base + off) = hi;
    *(__nv_bfloat16*)(base + WIMG_B + off) = lo;
}

// ---------------- HMMA GEMM: out[128,128] tile = A @ W (+bias, opt softplus, opt residual) ----------------
template<int ACT, int RES>
__global__ void __launch_bounds__(256) k_gemm_mma(
        const float* __restrict__ A, const char* __restrict__ wimg,
        const float* __restrict__ bias, const float* __restrict__ res,
        float* __restrict__ out){
    extern __shared__ __align__(16) char smem[];
    uint32_t sb = smem_u32(smem);
    int tid = threadIdx.x, wid = tid>>5, lane = tid&31;
    int row0 = blockIdx.x*128;

    // copy prebuilt W images (hi+lo = 69632 B)
    {
        const uint4* s = (const uint4*)wimg;
        uint4* d = (uint4*)(smem + SM_W_HI);
        #pragma unroll
        for(int i=0;i<17;i++){
            int j = i*256 + tid;
            if(j < 2*WIMG_B/16) d[j] = s[j];
        }
    }
    // stage A as bf16 hi/lo padded images
    {
        const float4* A4 = (const float4*)A;
        #pragma unroll 4
        for(int j=0;j<16;j++){
            int idx = j*256 + tid;          // 4096 float4 = 128 rows x 32
            int row = idx >> 5;
            int c4  = (idx & 31) << 2;
            float4 a = A4[(size_t)(row0+row)*32 + (idx&31)];
            __nv_bfloat16 h0=__float2bfloat16(a.x), h1=__float2bfloat16(a.y);
            __nv_bfloat16 h2=__float2bfloat16(a.z), h3=__float2bfloat16(a.w);
            __nv_bfloat16 l0=__float2bfloat16(a.x-__bfloat162float(h0));
            __nv_bfloat16 l1=__float2bfloat16(a.y-__bfloat162float(h1));
            __nv_bfloat16 l2=__float2bfloat16(a.z-__bfloat162float(h2));
            __nv_bfloat16 l3=__float2bfloat16(a.w-__bfloat162float(h3));
            int off = (row*WPAD + c4)*2;
            *(__nv_bfloat162*)(smem + SM_A_HI + off  ) = __nv_bfloat162(h0,h1);
            *(__nv_bfloat162*)(smem + SM_A_HI + off+4) = __nv_bfloat162(h2,h3);
            *(__nv_bfloat162*)(smem + SM_A_LO + off  ) = __nv_bfloat162(l0,l1);
            *(__nv_bfloat162*)(smem + SM_A_LO + off+4) = __nv_bfloat162(l2,l3);
        }
    }
    __syncthreads();

    // per-lane ldmatrix address components
    int i4 = lane>>3, r8 = lane&7;
    int a_row    = wid*16 + r8 + (i4&1)*8;
    int a_coladd = (i4>>1)*8;
    int b_radd   = (i4>>1)*8 + r8;     // within a 16-col (2-nfrag) group
    int b_coladd = (i4&1)*8;

    float acc[64];
    #pragma unroll
    for(int i=0;i<64;i++) acc[i]=0.f;

    #pragma unroll
    for(int ks=0; ks<8; ks++){
        int k0 = ks*16;
        uint32_t aoff = (uint32_t)(a_row*WPAD + k0 + a_coladd)*2;
        uint32_t ahi[4], alo[4];
        ldsm4(sb + SM_A_HI + aoff, ahi);
        ldsm4(sb + SM_A_LO + aoff, alo);
        #pragma unroll
        for(int p=0;p<8;p++){
            uint32_t boff = (uint32_t)((p*16 + b_radd)*WPAD + k0 + b_coladd)*2;
            uint32_t bh[4], bl[4];
            ldsm4(sb + SM_W_HI + boff, bh);
            ldsm4(sb + SM_W_LO + boff, bl);
            float* c0 = acc + (2*p  )*4;
            float* c1 = acc + (2*p+1)*4;
            mma16816(c0, ahi, bh[0], bh[1]);
            mma16816(c1, ahi, bh[2], bh[3]);
            mma16816(c0, ahi, bl[0], bl[1]);
            mma16816(c1, ahi, bl[2], bl[3]);
            mma16816(c0, alo, bh[0], bh[1]);
            mma16816(c1, alo, bh[2], bh[3]);
        }
    }

    // epilogue: write C fragments straight to gmem
    int rA = row0 + wid*16 + (lane>>2);
    int rB = rA + 8;
    #pragma unroll
    for(int f=0; f<16; f++){
        int col0 = f*8 + 2*(lane&3);
        float b0 = __ldg(bias + col0), b1 = __ldg(bias + col0 + 1);
        float v0 = acc[f*4+0] + b0, v1 = acc[f*4+1] + b1;
        float v2 = acc[f*4+2] + b0, v3 = acc[f*4+3] + b1;
        if(ACT){ v0=sp_f(v0); v1=sp_f(v1); v2=sp_f(v2); v3=sp_f(v3); }
        if(RES){
            const float2 rr0 = *(const float2*)(res + (size_t)rA*HID + col0);
            const float2 rr1 = *(const float2*)(res + (size_t)rB*HID + col0);
            v0+=rr0.x; v1+=rr0.y; v2+=rr1.x; v3+=rr1.y;
        }
        *(float2*)(out + (size_t)rA*HID + col0) = make_float2(v0, v1);
        *(float2*)(out + (size_t)rB*HID + col0) = make_float2(v2, v3);
    }
}

// ---------------- edge features ----------------
__global__ void k_efeat(const float* __restrict__ pos, const float* __restrict__ ew,
                        const int* __restrict__ ei){
    int e = blockIdx.x*256 + threadIdx.x;
    if(e >= NE) return;
    int s = ei[e], d = ei[NE+e];
    float dx = pos[d*3+0]-pos[s*3+0];
    float dy = pos[d*3+1]-pos[s*3+1];
    float dz = pos[d*3+2]-pos[s*3+2];
    float D  = sqrtf(dx*dx+dy*dy+dz*dz);
    float x  = D*0.1f;
    float cut = 0.f;
    if(x < 1.f){
        float x3=x*x*x, x4=x3*x, x5=x4*x;
        cut = 1.f - 6.f*x5 + 15.f*x4 - 10.f*x3;
    }
    float ed = expf(-D);
    const float cK = expf(-10.f);
    const float dc = (cK - 1.f)/8.f;
    float w = 4.5f/(1.f - cK); w = w*w;
    #pragma unroll
    for(int r=0;r<9;r++){
        float c = 1.f + (float)r*dc;
        float t = ed - c;
        g_efeat[e*10+r] = cut * expf(-w*t*t);
    }
    g_efeat[e*10+9] = ew[e];
}

// ---------------- CSR build ----------------
__global__ void k_hist(const int* __restrict__ ei){
    int e = blockIdx.x*256 + threadIdx.x;
    if(e < NE) atomicAdd(&g_deg[ei[NE+e]], 1);
}
__global__ void k_scan(){
    __shared__ int sd[1024];
    __shared__ int carry;
    int tid = threadIdx.x;
    if(tid==0) carry = 0;
    __syncthreads();
    for(int base=0; base<NN; base+=1024){
        int i = base + tid;
        int v = (i < NN) ? g_deg[i] : 0;
        sd[tid] = v; __syncthreads();
        #pragma unroll
        for(int off=1; off<1024; off<<=1){
            int t = (tid >= off) ? sd[tid-off] : 0;
            __syncthreads();
            sd[tid] += t;
            __syncthreads();
        }
        if(i < NN) g_rowptr[i] = carry + sd[tid] - v;
        int total = sd[1023];
        __syncthreads();
        if(tid==0) carry += total;
        __syncthreads();
    }
    if(tid==0) g_rowptr[NN] = carry;
}
__global__ void k_scatter(const int* __restrict__ ei){
    int e = blockIdx.x*256 + threadIdx.x;
    if(e >= NE) return;
    int d = ei[NE+e];
    int p = atomicAdd(&g_cursor[d], 1);
    g_csr[g_rowptr[d] + p] = e;
}

// ---------------- LayerNorm ----------------
__global__ void k_ln(const float* __restrict__ gam, const float* __restrict__ bet){
    int n = blockIdx.x*4 + (threadIdx.x>>5);
    if(n >= NPAD) return;
    int lane = threadIdx.x & 31;
    float4 x = ((const float4*)g_h)[n*32 + lane];
    float s  = x.x+x.y+x.z+x.w;
    float ss = x.x*x.x+x.y*x.y+x.z*x.z+x.w*x.w;
    #pragma unroll
    for(int o=16;o;o>>=1){
        s  += __shfl_xor_sync(0xffffffffu, s,  o);
        ss += __shfl_xor_sync(0xffffffffu, ss, o);
    }
    float mean = s*(1.f/128.f);
    float var  = ss*(1.f/128.f) - mean*mean;
    float inv  = rsqrtf(var + 1e-5f);
    float4 g4 = ((const float4*)gam)[lane];
    float4 b4 = ((const float4*)bet)[lane];
    float4 y;
    y.x=(x.x-mean)*inv*g4.x+b4.x;
    y.y=(x.y-mean)*inv*g4.y+b4.y;
    y.z=(x.z-mean)*inv*g4.z+b4.z;
    y.w=(x.w-mean)*inv*g4.w+b4.w;
    ((float4*)g_hn)[n*32 + lane] = y;
}

// ---------------- attention: logits + running max ----------------
__global__ void k_logits(const int* __restrict__ ei, const float* __restrict__ We){
    int e = blockIdx.x*4 + (threadIdx.x>>5);
    if(e >= NE) return;
    int lane = threadIdx.x & 31;
    int s = ei[e], d = ei[NE+e];
    float4 q4 = ((const float4*)g_q)[d*32 + lane];
    float4 k4 = ((const float4*)g_k)[s*32 + lane];
    float4 ea = make_float4(0.f,0.f,0.f,0.f);
    #pragma unroll
    for(int r=0;r<10;r++){
        float ef = g_efeat[e*10+r];
        float4 w = ((const float4*)We)[r*32 + lane];
        ea.x += ef*w.x; ea.y += ef*w.y; ea.z += ef*w.z; ea.w += ef*w.w;
    }
    float p = q4.x*(k4.x+ea.x) + q4.y*(k4.y+ea.y) + q4.z*(k4.z+ea.z) + q4.w*(k4.w+ea.w);
    p += __shfl_xor_sync(0xffffffffu, p, 1);
    p += __shfl_xor_sync(0xffffffffu, p, 2);
    p += __shfl_xor_sync(0xffffffffu, p, 4);
    if((lane&7)==0){
        int head = lane>>3;
        float l = p * 0.17677669529663687f;
        g_w[e*4 + head] = l;
        atomicMax(&g_maxi[d*4 + head], fkey(l));
    }
}

// ---------------- attention: exp + segment sum (edge-parallel) ----------------
__global__ void k_expw(const int* __restrict__ ei){
    int idx = blockIdx.x*256 + threadIdx.x;
    if(idx >= NE*4) return;
    int e = idx>>2, h2 = idx&3;
    int d = ei[NE+e];
    float m = funkey(g_maxi[d*4 + h2]);
    float w = expf(g_w[idx] - m);
    atomicAdd(&g_ssum[d*4 + h2], w);
    g_w[idx] = w;
}

// ---------------- attention aggregate + gated skip + residual (fused) ----------------
__global__ void k_agg(const int* __restrict__ ei, const float* __restrict__ We,
                      const float* __restrict__ Wb){
    int n = blockIdx.x*4 + (threadIdx.x>>5);
    if(n >= NN) return;
    int lane = threadIdx.x & 31, head = lane>>3;
    int row = g_rowptr[n];
    int deg = g_rowptr[n+1] - row;
    float4 w_e[10];
    #pragma unroll
    for(int r=0;r<10;r++) w_e[r] = ((const float4*)We)[r*32 + lane];
    float4 acc = make_float4(0.f,0.f,0.f,0.f);
    for(int i=0;i<deg;i++){
        int e = g_csr[row+i];
        int s = ei[e];
        float w = g_w[e*4 + head];
        float4 v4 = ((const float4*)g_v)[s*32 + lane];
        float4 ea = make_float4(0.f,0.f,0.f,0.f);
        #pragma unroll
        for(int r=0;r<10;r++){
            float ef = g_efeat[e*10+r];
            ea.x += ef*w_e[r].x; ea.y += ef*w_e[r].y;
            ea.z += ef*w_e[r].z; ea.w += ef*w_e[r].w;
        }
        acc.x += w*(v4.x+ea.x); acc.y += w*(v4.y+ea.y);
        acc.z += w*(v4.z+ea.z); acc.w += w*(v4.w+ea.w);
    }
    float inv = (deg>0) ? 1.f/g_ssum[n*4+head] : 0.f;
    float4 o; o.x=acc.x*inv; o.y=acc.y*inv; o.z=acc.z*inv; o.w=acc.w*inv;
    // fused beta-gate + softplus residual
    float4 x  = ((const float4*)g_xr)[n*32+lane];
    float4 hn = ((const float4*)g_hn)[n*32+lane];
    float4 w0 = ((const float4*)Wb)[lane];
    float4 w1 = ((const float4*)Wb)[32+lane];
    float4 w2 = ((const float4*)Wb)[64+lane];
    float p = o.x*w0.x + o.y*w0.y + o.z*w0.z + o.w*w0.w
            + x.x*w1.x + x.y*w1.y + x.z*w1.z + x.w*w1.w
            + (o.x-x.x)*w2.x + (o.y-x.y)*w2.y + (o.z-x.z)*w2.z + (o.w-x.w)*w2.w;
    #pragma unroll
    for(int off=16;off;off>>=1) p += __shfl_xor_sync(0xffffffffu, p, off);
    float beta = 1.f/(1.f+expf(-p));
    float4 r;
    r.x = beta*x.x + (1.f-beta)*o.x;
    r.y = beta*x.y + (1.f-beta)*o.y;
    r.z = beta*x.z + (1.f-beta)*o.z;
    r.w = beta*x.w + (1.f-beta)*o.w;
    float4 hout;
    hout.x = hn.x + sp_f(r.x); hout.y = hn.y + sp_f(r.y);
    hout.z = hn.z + sp_f(r.z); hout.w = hn.w + sp_f(r.w);
    ((float4*)g_h)[n*32+lane] = hout;
}

// ---------------- pooling + head ----------------
__global__ void k_pool(const int* __restrict__ batch){
    int n = blockIdx.x*4 + (threadIdx.x>>5);
    if(n >= NN) return;
    int lane = threadIdx.x & 31;
    int g = batch[n];
    float4 v = ((const float4*)g_h)[n*32+lane];
    float* base = &g_pooled[g*HID + 4*lane];
    atomicAdd(base+0, v.x); atomicAdd(base+1, v.y);
    atomicAdd(base+2, v.z); atomicAdd(base+3, v.w);
}
__global__ void k_final(const float* __restrict__ Wo1, const float* __restrict__ bo1,
                        const float* __restrict__ Wo2, const float* __restrict__ bo2,
                        float* __restrict__ out){
    int g = blockIdx.x*4 + (threadIdx.x>>5);
    if(g >= NG) return;
    int lane = threadIdx.x & 31;
    float4 acc = ((const float4*)bo1)[lane];
    const float* p = &g_pooled[g*HID];
    for(int k2=0;k2<HID;k2++){
        float a = p[k2];
        float4 w = ((const float4*)Wo1)[k2*32 + lane];
        acc.x += a*w.x; acc.y += a*w.y; acc.z += a*w.z; acc.w += a*w.w;
    }
    float4 w2 = ((const float4*)Wo2)[lane];
    float r = sp_f(acc.x)*w2.x + sp_f(acc.y)*w2.y + sp_f(acc.z)*w2.z + sp_f(acc.w)*w2.w;
    #pragma unroll
    for(int off=16;off;off>>=1) r += __shfl_xor_sync(0xffffffffu, r, off);
    if(lane==0) out[g] = r + bo2[0];
}

// ---------------- driver ----------------
extern "C" void kernel_launch(void* const* d_in, const int* in_sizes, int n_in,
                              void* d_out, int out_size){
    const float* h   = (const float*)d_in[0];
    const float* pos = (const float*)d_in[1];
    const float* ew  = (const float*)d_in[2];
    const float* Wq  = (const float*)d_in[3];  const float* bq = (const float*)d_in[4];
    const float* Wk  = (const float*)d_in[5];  const float* bk = (const float*)d_in[6];
    const float* Wv  = (const float*)d_in[7];  const float* bv = (const float*)d_in[8];
    const float* We  = (const float*)d_in[9];
    const float* Ws  = (const float*)d_in[10]; const float* bs = (const float*)d_in[11];
    const float* Wb  = (const float*)d_in[12];
    const float* W1  = (const float*)d_in[13]; const float* b1 = (const float*)d_in[14];
    const float* W2  = (const float*)d_in[15]; const float* b2 = (const float*)d_in[16];
    const float* W3  = (const float*)d_in[17]; const float* b3 = (const float*)d_in[18];
    const float* lgm = (const float*)d_in[19]; const float* lbt = (const float*)d_in[20];
    const float* Wo1 = (const float*)d_in[21]; const float* bo1 = (const float*)d_in[22];
    const float* Wo2 = (const float*)d_in[23]; const float* bo2 = (const float*)d_in[24];
    const int*   ei  = (const int*)d_in[25];
    const int*   bat = (const int*)d_in[26];
    float* out = (float*)d_out;

    float *p_hn,*p_q,*p_k,*p_v,*p_xr,*p_h,*p_f1,*p_f2;
    char* p_wimg;
    cudaGetSymbolAddress((void**)&p_h,  g_h);
    cudaGetSymbolAddress((void**)&p_hn, g_hn);
    cudaGetSymbolAddress((void**)&p_q,  g_q);
    cudaGetSymbolAddress((void**)&p_k,  g_k);
    cudaGetSymbolAddress((void**)&p_v,  g_v);
    cudaGetSymbolAddress((void**)&p_xr, g_xr);
    cudaGetSymbolAddress((void**)&p_f1, g_f1);
    cudaGetSymbolAddress((void**)&p_f2, g_f2);
    cudaGetSymbolAddress((void**)&p_wimg, g_wimg);

    cudaFuncSetAttribute(k_gemm_mma<0,0>, cudaFuncAttributeMaxDynamicSharedMemorySize, SM_BYTES);
    cudaFuncSetAttribute(k_gemm_mma<1,0>, cudaFuncAttributeMaxDynamicSharedMemorySize, SM_BYTES);
    cudaFuncSetAttribute(k_gemm_mma<1,1>, cudaFuncAttributeMaxDynamicSharedMemorySize, SM_BYTES);

    k_init    <<<(NPAD*HID+255)/256, 256>>>(h);
    k_zero_all<<<(NG*HID+255)/256, 256>>>();
    k_prepw   <<<(21*16384)/256, 256>>>(Wq, Wk, Wv, Ws, W1, W2, W3);
    k_efeat   <<<(NE+255)/256, 256>>>(pos, ew, ei);
    k_hist    <<<(NE+255)/256, 256>>>(ei);
    k_scan    <<<1, 1024>>>();
    k_scatter <<<(NE+255)/256, 256>>>(ei);

    const int NB = NPAD/128; // 391
    for(int i=0;i<NLAY;i++){
        const float* bqi=bq+i*HID; const float* bki=bk+i*HID;
        const float* bvi=bv+i*HID; const float* bsi=bs+i*HID;
        const float* Wei=We+i*10*HID;
        const float* Wbi=Wb+i*3*HID;
        const float* b1i=b1+i*HID; const float* b2i=b2+i*HID; const float* b3i=b3+i*HID;
        #define WIMG(fam) (p_wimg + (size_t)((fam)*3 + i)*WMAT_B)

        k_ln<<<NPAD/4, 128>>>(lgm, lbt);
        k_zero_attn<<<(NN*4+255)/256, 256>>>();
        k_gemm_mma<0,0><<<NB, 256, SM_BYTES>>>(p_hn, WIMG(0), bqi, nullptr, p_q);
        k_gemm_mma<0,0><<<NB, 256, SM_BYTES>>>(p_hn, WIMG(1), bki, nullptr, p_k);
        k_gemm_mma<0,0><<<NB, 256, SM_BYTES>>>(p_hn, WIMG(2), bvi, nullptr, p_v);
        k_gemm_mma<0,0><<<NB, 256, SM_BYTES>>>(p_hn, WIMG(3), bsi, nullptr, p_xr);
        k_logits<<<NE/4, 128>>>(ei, Wei);
        k_expw  <<<(NE*4)/256, 256>>>(ei);
        k_agg   <<<(NN+3)/4, 128>>>(ei, Wei, Wbi);
        k_ln<<<NPAD/4, 128>>>(lgm, lbt);
        k_gemm_mma<1,0><<<NB, 256, SM_BYTES>>>(p_hn, WIMG(4), b1i, nullptr, p_f1);
        k_gemm_mma<1,0><<<NB, 256, SM_BYTES>>>(p_f1, WIMG(5), b2i, nullptr, p_f2);
        k_gemm_mma<1,1><<<NB, 256, SM_BYTES>>>(p_f2, WIMG(6), b3i, p_hn, p_h);
        #undef WIMG
    }

    k_pool <<<(NN+3)/4, 128>>>(bat);
    k_final<<<NG/4, 128>>>(Wo1, bo1, Wo2, bo2, out);
}

// round 5
// speedup vs baseline: 1.6634x; 1.6634x over previous
#include <cuda_runtime.h>
#include <cuda_bf16.h>
#include <cstdint>

#define NN   50000
#define NPAD 50048          // 391 * 128
#define NE   400000
#define HID  128
#define NLAY 3
#define NG   512

#define WPAD 136            // padded row length (halves): ldmatrix conflict-free (272B stride)
#define WIMG_B (128*WPAD*2) // 34816 bytes per bf16 image
#define WMAT_B (2*WIMG_B)   // hi + lo per matrix = 69632

// ---------------- scratch ----------------
__device__ float g_h  [NPAD*HID];
__device__ float g_hn [NPAD*HID];
__device__ float g_q  [NPAD*HID];
__device__ float g_k  [NPAD*HID];
__device__ float g_v  [NPAD*HID];
__device__ float g_xr [NPAD*HID];
__device__ float g_f1 [NPAD*HID];
__device__ float g_f2 [NPAD*HID];
__device__ float g_efeat[NE*10];
__device__ float g_w   [NE*4];
__device__ unsigned g_maxi[NN*4];
__device__ float    g_ssum[NN*4];
__device__ int   g_deg[NN];
__device__ int   g_rowptr[NN+1];
__device__ int   g_cursor[NN];
__device__ int   g_csr[NE];
__device__ float g_pooled[NG*HID];
__device__ __align__(128) char g_wimg[21*WMAT_B];

__device__ __forceinline__ float sp_f(float x){ return x > 20.f ? x : log1pf(expf(x)); }

__device__ __forceinline__ unsigned fkey(float f){
    unsigned b = __float_as_uint(f);
    return (b & 0x80000000u) ? ~b : (b | 0x80000000u);
}
__device__ __forceinline__ float funkey(unsigned k){
    unsigned b = (k & 0x80000000u) ? (k & 0x7fffffffu) : ~k;
    return __uint_as_float(b);
}

__device__ __forceinline__ uint32_t smem_u32(const void* p){
    uint32_t a;
    asm("{ .reg .u64 t; cvta.to.shared.u64 t, %1; cvt.u32.u64 %0, t; }" : "=r"(a) : "l"(p));
    return a;
}
__device__ __forceinline__ void ldsm4(uint32_t addr, uint32_t* r){
    asm volatile("ldmatrix.sync.aligned.m8n8.x4.shared.b16 {%0,%1,%2,%3}, [%4];"
        : "=r"(r[0]), "=r"(r[1]), "=r"(r[2]), "=r"(r[3]) : "r"(addr));
}
__device__ __forceinline__ void mma16816(float* c, const uint32_t* a, uint32_t b0, uint32_t b1){
    asm volatile(
        "mma.sync.aligned.m16n8k16.row.col.f32.bf16.bf16.f32 "
        "{%0,%1,%2,%3}, {%4,%5,%6,%7}, {%8,%9}, {%0,%1,%2,%3};"
        : "+f"(c[0]), "+f"(c[1]), "+f"(c[2]), "+f"(c[3])
        : "r"(a[0]), "r"(a[1]), "r"(a[2]), "r"(a[3]), "r"(b0), "r"(b1));
}
__device__ __forceinline__ void cp16(uint32_t saddr, const void* gptr){
    asm volatile("cp.async.cg.shared.global [%0], [%1], 16;" :: "r"(saddr), "l"(gptr));
}
#define CP_COMMIT() asm volatile("cp.async.commit_group;" ::: "memory")
#define CP_WAIT(n)  asm volatile("cp.async.wait_group %0;" :: "n"(n) : "memory")

// ---------------- init / zero ----------------
__global__ void k_init(const float* __restrict__ h){
    int i = blockIdx.x*256 + threadIdx.x;
    if(i < NPAD*HID) g_h[i] = (i < NN*HID) ? h[i] : 0.f;
}
__global__ void k_zero_all(){
    int i = blockIdx.x*256 + threadIdx.x;
    if(i < NN){ g_deg[i] = 0; g_cursor[i] = 0; }
    if(i < NG*HID) g_pooled[i] = 0.f;
}
__global__ void k_zero_attn(){
    int i = blockIdx.x*256 + threadIdx.x;
    if(i < NN*4){ g_maxi[i] = 0u; g_ssum[i] = 0.f; }
}

// ---------------- weight prep: W^T + bf16 hi/lo padded images ----------------
__global__ void k_prepw(const float* Wq, const float* Wk, const float* Wv, const float* Ws,
                        const float* W1, const float* W2, const float* W3){
    int idx = blockIdx.x*256 + threadIdx.x;
    if(idx >= 21*16384) return;
    int m = idx >> 14;
    int within = idx & 16383;
    int n = within >> 7, k2 = within & 127;
    int fam = m/3, layer = m - fam*3;
    const float* W;
    switch(fam){
        case 0: W = Wq; break; case 1: W = Wk; break; case 2: W = Wv; break;
        case 3: W = Ws; break; case 4: W = W1; break; case 5: W = W2; break;
        default: W = W3; break;
    }
    float w = W[layer*16384 + k2*128 + n];       // Wt[n][k] = W[k][n]
    __nv_bfloat16 hi = __float2bfloat16(w);
    __nv_bfloat16 lo = __float2bfloat16(w - __bfloat162float(hi));
    char* base = g_wimg + (size_t)m*WMAT_B;
    int off = (n*WPAD + k2)*2;
    *(__nv_bfloat16*)(base + off) = hi;
    *(__nv_bfloat16*)(base + WIMG_B + off) = lo;
}

// ---------------- shared GEMM pieces (512 threads, 16 warps: 8 M x 2 N) ----------------
// A image (hi at sbA, lo at sbA+WIMG_B); W image (hi at sbW, lo at sbW+WIMG_B)
__device__ __forceinline__ void stage_A(char* smem, const float* __restrict__ A, int row0, int tid){
    const float4* A4 = (const float4*)A;
    #pragma unroll
    for(int j=0;j<8;j++){
        int idx = j*512 + tid;          // 4096 float4 = 128 rows x 32
        int row = idx >> 5;
        int c4  = (idx & 31) << 2;
        float4 a = A4[(size_t)(row0+row)*32 + (idx&31)];
        __nv_bfloat16 h0=__float2bfloat16(a.x), h1=__float2bfloat16(a.y);
        __nv_bfloat16 h2=__float2bfloat16(a.z), h3=__float2bfloat16(a.w);
        __nv_bfloat16 l0=__float2bfloat16(a.x-__bfloat162float(h0));
        __nv_bfloat16 l1=__float2bfloat16(a.y-__bfloat162float(h1));
        __nv_bfloat16 l2=__float2bfloat16(a.z-__bfloat162float(h2));
        __nv_bfloat16 l3=__float2bfloat16(a.w-__bfloat162float(h3));
        int off = (row*WPAD + c4)*2;
        *(__nv_bfloat162*)(smem + off  )          = __nv_bfloat162(h0,h1);
        *(__nv_bfloat162*)(smem + off+4)          = __nv_bfloat162(h2,h3);
        *(__nv_bfloat162*)(smem + WIMG_B + off  ) = __nv_bfloat162(l0,l1);
        *(__nv_bfloat162*)(smem + WIMG_B + off+4) = __nv_bfloat162(l2,l3);
    }
}
__device__ __forceinline__ void prefetch_W(uint32_t sbW, const char* __restrict__ wsrc, int tid){
    #pragma unroll
    for(int j=0;j<9;j++){
        int c = j*512 + tid;                 // 4352 16B chunks
        if(c < WMAT_B/16) cp16(sbW + c*16, wsrc + c*16);
    }
}
__device__ __forceinline__ void mma_tile(uint32_t sbA, uint32_t sbW, float* acc, int wm, int wn, int lane){
    int i4 = lane>>3, r8 = lane&7;
    int a_row = wm*16 + r8 + (i4&1)*8;
    int a_col = (i4>>1)*8;
    int b_row = wn*64 + (i4>>1)*8 + r8;
    int b_col = (i4&1)*8;
    #pragma unroll
    for(int ks=0; ks<8; ks++){
        int k0 = ks*16;
        uint32_t aoff = (uint32_t)(a_row*WPAD + k0 + a_col)*2;
        uint32_t ahi[4], alo[4];
        ldsm4(sbA + aoff, ahi);
        ldsm4(sbA + WIMG_B + aoff, alo);
        #pragma unroll
        for(int p=0;p<4;p++){
            uint32_t boff = (uint32_t)((b_row + p*16)*WPAD + k0 + b_col)*2;
            uint32_t bh[4], bl[4];
            ldsm4(sbW + boff, bh);
            ldsm4(sbW + WIMG_B + boff, bl);
            float* c0 = acc + p*8;
            float* c1 = acc + p*8 + 4;
            mma16816(c0, ahi, bh[0], bh[1]);
            mma16816(c1, ahi, bh[2], bh[3]);
            mma16816(c0, ahi, bl[0], bl[1]);
            mma16816(c1, ahi, bl[2], bl[3]);
            mma16816(c0, alo, bh[0], bh[1]);
            mma16816(c1, alo, bh[2], bh[3]);
        }
    }
}
template<int ACT, int RES>
__device__ __forceinline__ void epilogue(const float* acc, const float* __restrict__ bias,
                                         const float* __restrict__ res, float* __restrict__ out,
                                         int row0, int wm, int wn, int lane){
    int rA = row0 + wm*16 + (lane>>2);
    int rB = rA + 8;
    #pragma unroll
    for(int f=0; f<8; f++){
        int idx = (f>>1)*8 + (f&1)*4;
        int col0 = wn*64 + f*8 + 2*(lane&3);
        float b0 = __ldg(bias + col0), b1 = __ldg(bias + col0 + 1);
        float v0 = acc[idx+0] + b0, v1 = acc[idx+1] + b1;
        float v2 = acc[idx+2] + b0, v3 = acc[idx+3] + b1;
        if(ACT){ v0=sp_f(v0); v1=sp_f(v1); v2=sp_f(v2); v3=sp_f(v3); }
        if(RES){
            const float2 rr0 = *(const float2*)(res + (size_t)rA*HID + col0);
            const float2 rr1 = *(const float2*)(res + (size_t)rB*HID + col0);
            v0+=rr0.x; v1+=rr0.y; v2+=rr1.x; v3+=rr1.y;
        }
        *(float2*)(out + (size_t)rA*HID + col0) = make_float2(v0, v1);
        *(float2*)(out + (size_t)rB*HID + col0) = make_float2(v2, v3);
    }
}

// ---------------- fused QKVS GEMM: 4 matrices, double-buffered W pipeline ----------------
__global__ void __launch_bounds__(512) k_gemm4(
        const float* __restrict__ A, const char* __restrict__ wimg, int layer,
        const float* __restrict__ bq, const float* __restrict__ bk,
        const float* __restrict__ bv, const float* __restrict__ bs,
        float* __restrict__ oq, float* __restrict__ ok,
        float* __restrict__ ov, float* __restrict__ oxr){
    extern __shared__ __align__(16) char smem[];
    uint32_t sb = smem_u32(smem);
    int tid = threadIdx.x, wid = tid>>5, lane = tid&31;
    int wm = wid & 7, wn = wid >> 3;
    int row0 = blockIdx.x*128;
    const uint32_t sbA = sb;
    const uint32_t sbW0 = sb + WMAT_B;
    const uint32_t sbW1 = sb + 2*WMAT_B;

    prefetch_W(sbW0, wimg + (size_t)(0*3 + layer)*WMAT_B, tid);
    CP_COMMIT();
    stage_A(smem, A, row0, tid);

    const float* biases[4] = {bq + layer*HID, bk + layer*HID, bv + layer*HID, bs + layer*HID};
    float* outs[4] = {oq, ok, ov, oxr};

    #pragma unroll
    for(int m=0;m<4;m++){
        if(m<3){
            prefetch_W((m&1)?sbW0:sbW1, wimg + (size_t)((m+1)*3 + layer)*WMAT_B, tid);
            CP_COMMIT();
            CP_WAIT(1);
        } else {
            CP_WAIT(0);
        }
        __syncthreads();
        float acc[32];
        #pragma unroll
        for(int i=0;i<32;i++) acc[i]=0.f;
        mma_tile(sbA, (m&1)?sbW1:sbW0, acc, wm, wn, lane);
        __syncthreads();
        epilogue<0,0>(acc, biases[m], nullptr, outs[m], row0, wm, wn, lane);
    }
}

// ---------------- single GEMM (FFN) ----------------
template<int ACT, int RES>
__global__ void __launch_bounds__(512) k_gemm1(
        const float* __restrict__ A, const char* __restrict__ wimg,
        const float* __restrict__ bias, const float* __restrict__ res,
        float* __restrict__ out){
    extern __shared__ __align__(16) char smem[];
    uint32_t sb = smem_u32(smem);
    int tid = threadIdx.x, wid = tid>>5, lane = tid&31;
    int wm = wid & 7, wn = wid >> 3;
    int row0 = blockIdx.x*128;
    const uint32_t sbA = sb;
    const uint32_t sbW = sb + WMAT_B;

    prefetch_W(sbW, wimg, tid);
    CP_COMMIT();
    stage_A(smem, A, row0, tid);
    CP_WAIT(0);
    __syncthreads();

    float acc[32];
    #pragma unroll
    for(int i=0;i<32;i++) acc[i]=0.f;
    mma_tile(sbA, sbW, acc, wm, wn, lane);
    epilogue<ACT,RES>(acc, bias, res, out, row0, wm, wn, lane);
}

// ---------------- edge features ----------------
__global__ void k_efeat(const float* __restrict__ pos, const float* __restrict__ ew,
                        const int* __restrict__ ei){
    int e = blockIdx.x*256 + threadIdx.x;
    if(e >= NE) return;
    int s = ei[e], d = ei[NE+e];
    float dx = pos[d*3+0]-pos[s*3+0];
    float dy = pos[d*3+1]-pos[s*3+1];
    float dz = pos[d*3+2]-pos[s*3+2];
    float D  = sqrtf(dx*dx+dy*dy+dz*dz);
    float x  = D*0.1f;
    float cut = 0.f;
    if(x < 1.f){
        float x3=x*x*x, x4=x3*x, x5=x4*x;
        cut = 1.f - 6.f*x5 + 15.f*x4 - 10.f*x3;
    }
    float ed = expf(-D);
    const float cK = expf(-10.f);
    const float dc = (cK - 1.f)/8.f;
    float w = 4.5f/(1.f - cK); w = w*w;
    #pragma unroll
    for(int r=0;r<9;r++){
        float c = 1.f + (float)r*dc;
        float t = ed - c;
        g_efeat[e*10+r] = cut * expf(-w*t*t);
    }
    g_efeat[e*10+9] = ew[e];
}

// ---------------- CSR build ----------------
__global__ void k_hist(const int* __restrict__ ei){
    int e = blockIdx.x*256 + threadIdx.x;
    if(e < NE) atomicAdd(&g_deg[ei[NE+e]], 1);
}
__global__ void k_scan(){
    __shared__ int sd[1024];
    __shared__ int carry;
    int tid = threadIdx.x;
    if(tid==0) carry = 0;
    __syncthreads();
    for(int base=0; base<NN; base+=1024){
        int i = base + tid;
        int v = (i < NN) ? g_deg[i] : 0;
        sd[tid] = v; __syncthreads();
        #pragma unroll
        for(int off=1; off<1024; off<<=1){
            int t = (tid >= off) ? sd[tid-off] : 0;
            __syncthreads();
            sd[tid] += t;
            __syncthreads();
        }
        if(i < NN) g_rowptr[i] = carry + sd[tid] - v;
        int total = sd[1023];
        __syncthreads();
        if(tid==0) carry += total;
        __syncthreads();
    }
    if(tid==0) g_rowptr[NN] = carry;
}
__global__ void k_scatter(const int* __restrict__ ei){
    int e = blockIdx.x*256 + threadIdx.x;
    if(e >= NE) return;
    int d = ei[NE+e];
    int p = atomicAdd(&g_cursor[d], 1);
    g_csr[g_rowptr[d] + p] = e;
}

// ---------------- LayerNorm ----------------
__global__ void k_ln(const float* __restrict__ gam, const float* __restrict__ bet){
    int n = blockIdx.x*4 + (threadIdx.x>>5);
    if(n >= NPAD) return;
    int lane = threadIdx.x & 31;
    float4 x = ((const float4*)g_h)[n*32 + lane];
    float s  = x.x+x.y+x.z+x.w;
    float ss = x.x*x.x+x.y*x.y+x.z*x.z+x.w*x.w;
    #pragma unroll
    for(int o=16;o;o>>=1){
        s  += __shfl_xor_sync(0xffffffffu, s,  o);
        ss += __shfl_xor_sync(0xffffffffu, ss, o);
    }
    float mean = s*(1.f/128.f);
    float var  = ss*(1.f/128.f) - mean*mean;
    float inv  = rsqrtf(var + 1e-5f);
    float4 g4 = ((const float4*)gam)[lane];
    float4 b4 = ((const float4*)bet)[lane];
    float4 y;
    y.x=(x.x-mean)*inv*g4.x+b4.x;
    y.y=(x.y-mean)*inv*g4.y+b4.y;
    y.z=(x.z-mean)*inv*g4.z+b4.z;
    y.w=(x.w-mean)*inv*g4.w+b4.w;
    ((float4*)g_hn)[n*32 + lane] = y;
}

// ---------------- attention: logits + running max ----------------
__global__ void k_logits(const int* __restrict__ ei, const float* __restrict__ We){
    int e = blockIdx.x*4 + (threadIdx.x>>5);
    if(e >= NE) return;
    int lane = threadIdx.x & 31;
    int s = ei[e], d = ei[NE+e];
    float4 q4 = ((const float4*)g_q)[d*32 + lane];
    float4 k4 = ((const float4*)g_k)[s*32 + lane];
    float4 ea = make_float4(0.f,0.f,0.f,0.f);
    #pragma unroll
    for(int r=0;r<10;r++){
        float ef = g_efeat[e*10+r];
        float4 w = ((const float4*)We)[r*32 + lane];
        ea.x += ef*w.x; ea.y += ef*w.y; ea.z += ef*w.z; ea.w += ef*w.w;
    }
    float p = q4.x*(k4.x+ea.x) + q4.y*(k4.y+ea.y) + q4.z*(k4.z+ea.z) + q4.w*(k4.w+ea.w);
    p += __shfl_xor_sync(0xffffffffu, p, 1);
    p += __shfl_xor_sync(0xffffffffu, p, 2);
    p += __shfl_xor_sync(0xffffffffu, p, 4);
    if((lane&7)==0){
        int head = lane>>3;
        float l = p * 0.17677669529663687f;
        g_w[e*4 + head] = l;
        atomicMax(&g_maxi[d*4 + head], fkey(l));
    }
}

// ---------------- attention: exp + segment sum ----------------
__global__ void k_expw(const int* __restrict__ ei){
    int idx = blockIdx.x*256 + threadIdx.x;
    if(idx >= NE*4) return;
    int e = idx>>2, h2 = idx&3;
    int d = ei[NE+e];
    float m = funkey(g_maxi[d*4 + h2]);
    float w = expf(g_w[idx] - m);
    atomicAdd(&g_ssum[d*4 + h2], w);
    g_w[idx] = w;
}

// ---------------- attention aggregate + gated skip + residual ----------------
__global__ void k_agg(const int* __restrict__ ei, const float* __restrict__ We,
                      const float* __restrict__ Wb){
    int n = blockIdx.x*4 + (threadIdx.x>>5);
    if(n >= NN) return;
    int lane = threadIdx.x & 31, head = lane>>3;
    int row = g_rowptr[n];
    int deg = g_rowptr[n+1] - row;
    float4 w_e[10];
    #pragma unroll
    for(int r=0;r<10;r++) w_e[r] = ((const float4*)We)[r*32 + lane];
    float4 acc = make_float4(0.f,0.f,0.f,0.f);
    for(int i=0;i<deg;i++){
        int e = g_csr[row+i];
        int s = ei[e];
        float w = g_w[e*4 + head];
        float4 v4 = ((const float4*)g_v)[s*32 + lane];
        float4 ea = make_float4(0.f,0.f,0.f,0.f);
        #pragma unroll
        for(int r=0;r<10;r++){
            float ef = g_efeat[e*10+r];
            ea.x += ef*w_e[r].x; ea.y += ef*w_e[r].y;
            ea.z += ef*w_e[r].z; ea.w += ef*w_e[r].w;
        }
        acc.x += w*(v4.x+ea.x); acc.y += w*(v4.y+ea.y);
        acc.z += w*(v4.z+ea.z); acc.w += w*(v4.w+ea.w);
    }
    float inv = (deg>0) ? 1.f/g_ssum[n*4+head] : 0.f;
    float4 o; o.x=acc.x*inv; o.y=acc.y*inv; o.z=acc.z*inv; o.w=acc.w*inv;
    float4 x  = ((const float4*)g_xr)[n*32+lane];
    float4 hn = ((const float4*)g_hn)[n*32+lane];
    float4 w0 = ((const float4*)Wb)[lane];
    float4 w1 = ((const float4*)Wb)[32+lane];
    float4 w2 = ((const float4*)Wb)[64+lane];
    float p = o.x*w0.x + o.y*w0.y + o.z*w0.z + o.w*w0.w
            + x.x*w1.x + x.y*w1.y + x.z*w1.z + x.w*w1.w
            + (o.x-x.x)*w2.x + (o.y-x.y)*w2.y + (o.z-x.z)*w2.z + (o.w-x.w)*w2.w;
    #pragma unroll
    for(int off=16;off;off>>=1) p += __shfl_xor_sync(0xffffffffu, p, off);
    float beta = 1.f/(1.f+expf(-p));
    float4 r;
    r.x = beta*x.x + (1.f-beta)*o.x;
    r.y = beta*x.y + (1.f-beta)*o.y;
    r.z = beta*x.z + (1.f-beta)*o.z;
    r.w = beta*x.w + (1.f-beta)*o.w;
    float4 hout;
    hout.x = hn.x + sp_f(r.x); hout.y = hn.y + sp_f(r.y);
    hout.z = hn.z + sp_f(r.z); hout.w = hn.w + sp_f(r.w);
    ((float4*)g_h)[n*32+lane] = hout;
}

// ---------------- pooling + head ----------------
__global__ void k_pool(const int* __restrict__ batch){
    int n = blockIdx.x*4 + (threadIdx.x>>5);
    if(n >= NN) return;
    int lane = threadIdx.x & 31;
    int g = batch[n];
    float4 v = ((const float4*)g_h)[n*32+lane];
    float* base = &g_pooled[g*HID + 4*lane];
    atomicAdd(base+0, v.x); atomicAdd(base+1, v.y);
    atomicAdd(base+2, v.z); atomicAdd(base+3, v.w);
}
__global__ void k_final(const float* __restrict__ Wo1, const float* __restrict__ bo1,
                        const float* __restrict__ Wo2, const float* __restrict__ bo2,
                        float* __restrict__ out){
    int g = blockIdx.x*4 + (threadIdx.x>>5);
    if(g >= NG) return;
    int lane = threadIdx.x & 31;
    float4 acc = ((const float4*)bo1)[lane];
    const float* p = &g_pooled[g*HID];
    for(int k2=0;k2<HID;k2++){
        float a = p[k2];
        float4 w = ((const float4*)Wo1)[k2*32 + lane];
        acc.x += a*w.x; acc.y += a*w.y; acc.z += a*w.z; acc.w += a*w.w;
    }
    float4 w2 = ((const float4*)Wo2)[lane];
    float r = sp_f(acc.x)*w2.x + sp_f(acc.y)*w2.y + sp_f(acc.z)*w2.z + sp_f(acc.w)*w2.w;
    #pragma unroll
    for(int off=16;off;off>>=1) r += __shfl_xor_sync(0xffffffffu, r, off);
    if(lane==0) out[g] = r + bo2[0];
}

// ---------------- driver ----------------
extern "C" void kernel_launch(void* const* d_in, const int* in_sizes, int n_in,
                              void* d_out, int out_size){
    const float* h   = (const float*)d_in[0];
    const float* pos = (const float*)d_in[1];
    const float* ew  = (const float*)d_in[2];
    const float* Wq  = (const float*)d_in[3];  const float* bq = (const float*)d_in[4];
    const float* Wk  = (const float*)d_in[5];  const float* bk = (const float*)d_in[6];
    const float* Wv  = (const float*)d_in[7];  const float* bv = (const float*)d_in[8];
    const float* We  = (const float*)d_in[9];
    const float* Ws  = (const float*)d_in[10]; const float* bs = (const float*)d_in[11];
    const float* Wb  = (const float*)d_in[12];
    const float* W1  = (const float*)d_in[13]; const float* b1 = (const float*)d_in[14];
    const float* W2  = (const float*)d_in[15]; const float* b2 = (const float*)d_in[16];
    const float* W3  = (const float*)d_in[17]; const float* b3 = (const float*)d_in[18];
    const float* lgm = (const float*)d_in[19]; const float* lbt = (const float*)d_in[20];
    const float* Wo1 = (const float*)d_in[21]; const float* bo1 = (const float*)d_in[22];
    const float* Wo2 = (const float*)d_in[23]; const float* bo2 = (const float*)d_in[24];
    const int*   ei  = (const int*)d_in[25];
    const int*   bat = (const int*)d_in[26];
    float* out = (float*)d_out;

    float *p_hn,*p_q,*p_k,*p_v,*p_xr,*p_h,*p_f1,*p_f2;
    char* p_wimg;
    cudaGetSymbolAddress((void**)&p_h,  g_h);
    cudaGetSymbolAddress((void**)&p_hn, g_hn);
    cudaGetSymbolAddress((void**)&p_q,  g_q);
    cudaGetSymbolAddress((void**)&p_k,  g_k);
    cudaGetSymbolAddress((void**)&p_v,  g_v);
    cudaGetSymbolAddress((void**)&p_xr, g_xr);
    cudaGetSymbolAddress((void**)&p_f1, g_f1);
    cudaGetSymbolAddress((void**)&p_f2, g_f2);
    cudaGetSymbolAddress((void**)&p_wimg, g_wimg);

    const int SM4 = 3*WMAT_B;   // 208896
    const int SM1 = 2*WMAT_B;   // 139264
    cudaFuncSetAttribute(k_gemm4,      cudaFuncAttributeMaxDynamicSharedMemorySize, SM4);
    cudaFuncSetAttribute(k_gemm1<1,0>, cudaFuncAttributeMaxDynamicSharedMemorySize, SM1);
    cudaFuncSetAttribute(k_gemm1<1,1>, cudaFuncAttributeMaxDynamicSharedMemorySize, SM1);

    const int NB = NPAD/128; // 391

    // launch order chosen so launch #5 (0-based) is k_gemm4 -> gets profiled by ncu -s 5
    k_init    <<<(NPAD*HID+255)/256, 256>>>(h);                       // 0
    k_zero_all<<<(NG*HID+255)/256, 256>>>();                          // 1
    k_prepw   <<<(21*16384)/256, 256>>>(Wq, Wk, Wv, Ws, W1, W2, W3);  // 2
    k_ln      <<<NPAD/4, 128>>>(lgm, lbt);                            // 3
    k_zero_attn<<<(NN*4+255)/256, 256>>>();                           // 4
    k_gemm4   <<<NB, 512, SM4>>>(p_hn, p_wimg, 0, bq, bk, bv, bs,     // 5  <- profiled
                                 p_q, p_k, p_v, p_xr);
    k_efeat   <<<(NE+255)/256, 256>>>(pos, ew, ei);
    k_hist    <<<(NE+255)/256, 256>>>(ei);
    k_scan    <<<1, 1024>>>();
    k_scatter <<<(NE+255)/256, 256>>>(ei);

    for(int i=0;i<NLAY;i++){
        const float* Wei=We+i*10*HID;
        const float* Wbi=Wb+i*3*HID;
        const float* b1i=b1+i*HID; const float* b2i=b2+i*HID; const float* b3i=b3+i*HID;
        #define WIMG(fam) (p_wimg + (size_t)((fam)*3 + i)*WMAT_B)

        if(i>0){
            k_ln<<<NPAD/4, 128>>>(lgm, lbt);
            k_zero_attn<<<(NN*4+255)/256, 256>>>();
            k_gemm4<<<NB, 512, SM4>>>(p_hn, p_wimg, i, bq, bk, bv, bs, p_q, p_k, p_v, p_xr);
        }
        k_logits<<<NE/4, 128>>>(ei, Wei);
        k_expw  <<<(NE*4)/256, 256>>>(ei);
        k_agg   <<<(NN+3)/4, 128>>>(ei, Wei, Wbi);
        k_ln<<<NPAD/4, 128>>>(lgm, lbt);
        k_gemm1<1,0><<<NB, 512, SM1>>>(p_hn, WIMG(4), b1i, nullptr, p_f1);
        k_gemm1<1,0><<<NB, 512, SM1>>>(p_f1, WIMG(5), b2i, nullptr, p_f2);
        k_gemm1<1,1><<<NB, 512, SM1>>>(p_f2, WIMG(6), b3i, p_hn, p_h);
        #undef WIMG
    }

    k_pool <<<(NN+3)/4, 128>>>(bat);
    k_final<<<NG/4, 128>>>(Wo1, bo1, Wo2, bo2, out);
}